// round 1
// baseline (speedup 1.0000x reference)
#include <cuda_runtime.h>

// Problem constants (fixed shapes from the reference)
#define BB 16
#define TT 8192
#define CC 512
#define YY 256
#define C4 (CC / 4)   // 128 float4 lanes per row

// Scratch for span metadata (allocation-free: __device__ globals)
__device__ int g_start[BB * YY];
__device__ int g_count[BB * YY];

// ---------------------------------------------------------------------------
// Kernel 1: per-batch inclusive scan of durations -> clamped (start, count)
// grid = BB, block = YY (256 threads)
// ---------------------------------------------------------------------------
__global__ void __launch_bounds__(YY) span_prefix_kernel(const int* __restrict__ dur) {
    __shared__ int s[YY];
    const int b = blockIdx.x;
    const int y = threadIdx.x;
    const int v = dur[b * YY + y];
    s[y] = v;
    __syncthreads();
    // Hillis-Steele inclusive scan (read before sync, write after sync)
    #pragma unroll
    for (int off = 1; off < YY; off <<= 1) {
        int add = (y >= off) ? s[y - off] : 0;
        __syncthreads();
        s[y] += add;
        __syncthreads();
    }
    const int incl = s[y];        // cumulative end (unclamped)
    const int excl = incl - v;    // start (unclamped, >= 0 since durs >= 0)
    const int st = min(excl, TT);
    const int en = min(incl, TT);
    g_start[b * YY + y] = st;
    g_count[b * YY + y] = en - st;
}

// ---------------------------------------------------------------------------
// Kernel 2: mean-pool each span. One block per (b, y); 128 threads, each
// thread owns one float4 channel lane. Frame loop unrolled x4 with
// independent accumulators for memory-level parallelism.
// grid = BB*YY, block = 128
// ---------------------------------------------------------------------------
__global__ void __launch_bounds__(128) pool_kernel(const float* __restrict__ emg,
                                                   float* __restrict__ out) {
    const int by   = blockIdx.x;       // b * YY + y
    const int b    = by >> 8;          // YY == 256
    const int st   = g_start[by];
    const int cnt  = g_count[by];
    const int lane = threadIdx.x;      // 0..127

    const float4* p = reinterpret_cast<const float4*>(emg)
                      + ((size_t)b * TT + st) * C4 + lane;

    float4 a0 = make_float4(0.f, 0.f, 0.f, 0.f);
    float4 a1 = a0, a2 = a0, a3 = a0;

    int t = 0;
    for (; t + 4 <= cnt; t += 4) {
        float4 v0 = p[0 * C4];
        float4 v1 = p[1 * C4];
        float4 v2 = p[2 * C4];
        float4 v3 = p[3 * C4];
        a0.x += v0.x; a0.y += v0.y; a0.z += v0.z; a0.w += v0.w;
        a1.x += v1.x; a1.y += v1.y; a1.z += v1.z; a1.w += v1.w;
        a2.x += v2.x; a2.y += v2.y; a2.z += v2.z; a2.w += v2.w;
        a3.x += v3.x; a3.y += v3.y; a3.z += v3.z; a3.w += v3.w;
        p += 4 * C4;
    }
    for (; t < cnt; t++) {
        float4 v = p[0];
        a0.x += v.x; a0.y += v.y; a0.z += v.z; a0.w += v.w;
        p += C4;
    }

    const float inv = (cnt > 0) ? (1.0f / (float)cnt) : 0.0f;
    float4 r;
    r.x = (a0.x + a1.x + a2.x + a3.x) * inv;
    r.y = (a0.y + a1.y + a2.y + a3.y) * inv;
    r.z = (a0.z + a1.z + a2.z + a3.z) * inv;
    r.w = (a0.w + a1.w + a2.w + a3.w) * inv;

    reinterpret_cast<float4*>(out)[(size_t)by * C4 + lane] = r;
}

// ---------------------------------------------------------------------------
// Launch: metadata order is emg_feats (float32, B*T*C), durations (int32, B*Y)
// Output: float32 (B, Y, C)
// ---------------------------------------------------------------------------
extern "C" void kernel_launch(void* const* d_in, const int* in_sizes, int n_in,
                              void* d_out, int out_size) {
    const float* emg = (const float*)d_in[0];
    const int*   dur = (const int*)d_in[1];
    float*       out = (float*)d_out;

    span_prefix_kernel<<<BB, YY>>>(dur);
    pool_kernel<<<BB * YY, 128>>>(emg, out);
}